// round 11
// baseline (speedup 1.0000x reference)
#include <cuda_runtime.h>
#include <cuda_bf16.h>
#include <cstddef>

// NetAE batch-1 forward: HBM-bound GEMV chain (~596MB fp32 weights/call).
// Round 11 (base = round 8, 123.6us):
//  - fin_h2 / fin_res finalize kernels: C and F read an 8KB vector (MODE 0)
//    instead of re-reducing producer partials in every block (-45MB LTS).
//  - A/B/F at 512 blocks via GRP=2 (RPS=16 kept -> prologue coalescing
//    identical to r8, unlike the failed r10 RPS=8 variant). G at 256 blocks.
//  - fin_out widened to 8 blocks.
// DE/C main loops, PDL with end-of-kernel trigger: unchanged.

#define D_H    2048
#define D_A    256
#define N_EXP  16
#define D_OUT  512

__device__ float g_pA[256 * 2048];
__device__ float g_pB[256 * 2048];
__device__ float g_h2[2048];
__device__ float g_pC[16 * 32 * 2048];
__device__ float g_pD[16 * 256 * 256];   // 8 row-groups x 32 slices deep
__device__ float g_pE[512 * 2048];       // UNSCALED V partials
__device__ float g_res[2048];
__device__ float g_pF[256 * 2048];
__device__ float g_pG[512 * 512];
__device__ float g_ekq[16];

__device__ __forceinline__ float4 f4add(float4 a, float4 b) {
    return make_float4(a.x + b.x, a.y + b.y, a.z + b.z, a.w + b.w);
}

// ---------------------------------------------------------------------------
// Shared prologue (round-8 form): build sx[RPS] = x-slice [i0, i0+RPS).
//   MODE 0: sx[r] = xsrc[i0+r]
//   MODE 1: sx[r] = [relu](biasx[bb*NPREV+i0+r] + sum_{s<SPREV} xsrc[(bb*SPREV+s)*NPREV+i0+r])
// ---------------------------------------------------------------------------
template<int BLK, int RPS, int MODE, int SPREV, int NPREV, bool RELU_X, bool PREV_PER_B>
__device__ __forceinline__
void stage_x(float* sx, const float* __restrict__ xsrc,
             const float* __restrict__ biasx, int i0, int b)
{
    const int tid = threadIdx.x;
    if constexpr (MODE == 0) {
        for (int r = tid; r < RPS; r += BLK) sx[r] = xsrc[i0 + r];
        __syncthreads();
    } else {
        constexpr int NQ = RPS / 4;
        constexpr int CH = BLK / NQ;
        __shared__ float4 sxp4[BLK];
        const int q = tid % NQ;
        const int c = tid / NQ;
        const int bb = PREV_PER_B ? b : 0;
        const float4* p = reinterpret_cast<const float4*>(
            xsrc + ((size_t)bb * SPREV) * NPREV + i0);
        float4 v = make_float4(0.f, 0.f, 0.f, 0.f);
        #pragma unroll
        for (int s = c; s < SPREV; s += CH)
            v = f4add(v, p[(size_t)s * (NPREV / 4) + q]);
        sxp4[tid] = v;
        __syncthreads();
        if (tid < NQ) {
            float4 v2 = reinterpret_cast<const float4*>(
                            biasx + (size_t)bb * NPREV + i0)[tid];
            #pragma unroll
            for (int cc = 0; cc < CH; cc++) v2 = f4add(v2, sxp4[tid + cc * NQ]);
            if constexpr (RELU_X) {
                v2.x = fmaxf(v2.x, 0.f); v2.y = fmaxf(v2.y, 0.f);
                v2.z = fmaxf(v2.z, 0.f); v2.w = fmaxf(v2.w, 0.f);
            }
            reinterpret_cast<float4*>(sx)[tid] = v2;
        }
        __syncthreads();
    }
}

// Generic split-K GEMV stage. PF = rows prefetched into regs before the wait.
template<int BLK, int RPS, int N, int GRP, int MODE, int SPREV, int NPREV,
         bool RELU_X, bool PREV_PER_B, int PF>
__global__ __launch_bounds__(BLK)
void gemv_k(const float* __restrict__ W,
            const float* __restrict__ xsrc,
            const float* __restrict__ biasx,
            float* __restrict__ partOut)
{
    __shared__ float sx[RPS];
    const int tid   = threadIdx.x;
    const int slice = blockIdx.y;
    const int b     = blockIdx.z;
    const int S     = gridDim.y;
    const int i0    = slice * RPS;
    const int K     = S * RPS;

    constexpr int CT  = BLK / GRP;
    constexpr int RPG = RPS / GRP;
    const int g  = tid / CT;
    const int j  = (blockIdx.x * CT + (tid % CT)) * 4;
    const int r0 = g * RPG;
    const float* Wp = W + (size_t)b * K * N + (size_t)(i0 + r0) * N + j;

    float4 wreg[PF > 0 ? PF : 1];
    #pragma unroll
    for (int rr = 0; rr < PF; rr++)
        wreg[rr] = *reinterpret_cast<const float4*>(Wp + (size_t)rr * N);

    cudaGridDependencySynchronize();

    stage_x<BLK, RPS, MODE, SPREV, NPREV, RELU_X, PREV_PER_B>(sx, xsrc, biasx, i0, b);

    float4 acc = make_float4(0.f, 0.f, 0.f, 0.f);
    #pragma unroll
    for (int rr = 0; rr < PF; rr++) {
        const float xi = sx[r0 + rr];
        acc.x += xi * wreg[rr].x; acc.y += xi * wreg[rr].y;
        acc.z += xi * wreg[rr].z; acc.w += xi * wreg[rr].w;
    }
    #pragma unroll 16
    for (int rr = PF; rr < RPG; rr++) {
        const float4 w = *reinterpret_cast<const float4*>(Wp + (size_t)rr * N);
        const float xi = sx[r0 + rr];
        acc.x += xi * w.x; acc.y += xi * w.y;
        acc.z += xi * w.z; acc.w += xi * w.w;
    }
    *reinterpret_cast<float4*>(
        partOut + ((size_t)((b * S + slice) * GRP + g)) * N + j) = acc;
    cudaTriggerProgrammaticLaunchCompletion();
}

// ---------------------------------------------------------------------------
// Merged D+E stage, uniform 1024 blocks (round-8). grid = (2, 32, 16).
// ---------------------------------------------------------------------------
__global__ __launch_bounds__(256)
void gemv_DE(const float* __restrict__ Wv, const float* __restrict__ Wk,
             const float* __restrict__ pC, const float* __restrict__ b_exp,
             float* __restrict__ pE, float* __restrict__ pD)
{
    __shared__ float sx[64];
    const int tid   = threadIdx.x;
    const int xp    = blockIdx.x;
    const int slice = blockIdx.y;
    const int b     = blockIdx.z;
    const int i0    = slice * 64;

    cudaGridDependencySynchronize();
    stage_x<256, 64, 1, 32, 2048, true, true>(sx, pC, b_exp, i0, b);

    // ---- E tile ----
    {
        const int j = (xp * 256 + tid) * 4;
        const float* Wp = Wv + (size_t)b * 2048 * 2048 + (size_t)i0 * 2048 + j;
        float4 acc = make_float4(0.f, 0.f, 0.f, 0.f);
        #pragma unroll 16
        for (int rr = 0; rr < 64; rr++) {
            const float4 w = *reinterpret_cast<const float4*>(Wp + (size_t)rr * 2048);
            const float xi = sx[rr];
            acc.x += xi * w.x; acc.y += xi * w.y;
            acc.z += xi * w.z; acc.w += xi * w.w;
        }
        *reinterpret_cast<float4*>(pE + ((size_t)(b * 32 + slice)) * 2048 + j) = acc;
    }
    // ---- D tile ----
    {
        const int g  = tid / 32;
        const int jd = xp * 128 + (tid % 32) * 4;
        const int r0 = g * 8;
        const float* Wp = Wk + (size_t)b * 2048 * 256 + (size_t)(i0 + r0) * 256 + jd;
        float4 acc = make_float4(0.f, 0.f, 0.f, 0.f);
        #pragma unroll
        for (int rr = 0; rr < 8; rr++) {
            const float4 w = *reinterpret_cast<const float4*>(Wp + (size_t)rr * 256);
            const float xi = sx[r0 + rr];
            acc.x += xi * w.x; acc.y += xi * w.y;
            acc.z += xi * w.z; acc.w += xi * w.w;
        }
        *reinterpret_cast<float4*>(
            pD + ((size_t)((b * 32 + slice) * 8 + g)) * 256 + jd) = acc;
    }
    cudaTriggerProgrammaticLaunchCompletion();
}

// h2[j] = relu(b2[j] + reduce_{s<256} pB[s*2048+j]);  8 blocks x 256 thr.
__global__ __launch_bounds__(256)
void fin_h2(const float* __restrict__ part, const float* __restrict__ bias,
            float* __restrict__ outv)
{
    __shared__ float4 red4[256];
    const int q = blockIdx.x * 64 + (threadIdx.x % 64);   // quad in [0,512)
    const int c = threadIdx.x / 64;
    cudaGridDependencySynchronize();
    const float4* p = reinterpret_cast<const float4*>(part);
    float4 acc = make_float4(0.f, 0.f, 0.f, 0.f);
    #pragma unroll 8
    for (int s = c; s < 256; s += 4) acc = f4add(acc, p[(size_t)s * 512 + q]);
    red4[threadIdx.x] = acc;
    __syncthreads();
    if (c == 0) {
        float4 v = f4add(f4add(red4[threadIdx.x], red4[threadIdx.x + 64]),
                         f4add(red4[threadIdx.x + 128], red4[threadIdx.x + 192]));
        v = f4add(v, reinterpret_cast<const float4*>(bias)[q]);
        v.x = fmaxf(v.x, 0.f); v.y = fmaxf(v.y, 0.f);
        v.z = fmaxf(v.z, 0.f); v.w = fmaxf(v.w, 0.f);
        reinterpret_cast<float4*>(outv)[q] = v;
    }
    cudaTriggerProgrammaticLaunchCompletion();
}

// res[j] = sum_{row<512} ekq[row>>5]*pE[row*2048+j] + sum_n ekq[n]*b_v[n*2048+j]
__global__ __launch_bounds__(256)
void fin_res(const float* __restrict__ pE, const float* __restrict__ b_v,
             const float* __restrict__ ekq, float* __restrict__ res)
{
    __shared__ float4 red4[256];
    const int q = blockIdx.x * 64 + (threadIdx.x % 64);
    const int c = threadIdx.x / 64;
    cudaGridDependencySynchronize();
    const float4* p = reinterpret_cast<const float4*>(pE);
    float4 acc = make_float4(0.f, 0.f, 0.f, 0.f);
    #pragma unroll 8
    for (int s = c; s < 512; s += 4) {
        float4 w = p[(size_t)s * 512 + q];
        const float sc = ekq[s >> 5];
        acc.x += sc * w.x; acc.y += sc * w.y;
        acc.z += sc * w.z; acc.w += sc * w.w;
    }
    red4[threadIdx.x] = acc;
    __syncthreads();
    if (c == 0) {
        float4 v = f4add(f4add(red4[threadIdx.x], red4[threadIdx.x + 64]),
                         f4add(red4[threadIdx.x + 128], red4[threadIdx.x + 192]));
        #pragma unroll
        for (int n = 0; n < N_EXP; n++) {
            const float4 bq = reinterpret_cast<const float4*>(b_v + (size_t)n * 2048)[q];
            const float e = ekq[n];
            v.x += e * bq.x; v.y += e * bq.y;
            v.z += e * bq.z; v.w += e * bq.w;
        }
        reinterpret_cast<float4*>(res)[q] = v;
    }
    cudaTriggerProgrammaticLaunchCompletion();
}

// expkq[n] = (b_k[n] + reduce_{s<256} pD[n]) . (W_q[t][t] + b_q[t])
__global__ __launch_bounds__(256)
void fin_expkq(const float* __restrict__ part,
               const float* __restrict__ b_k,
               const float* __restrict__ W_q,
               const float* __restrict__ b_q,
               const int* __restrict__ task_id,
               float* __restrict__ expkq)
{
    __shared__ float4 red4[256];
    __shared__ float red[64];
    const int n = blockIdx.x;
    const int q = threadIdx.x % 64;
    const int c = threadIdx.x / 64;
    cudaGridDependencySynchronize();
    const int t = *task_id;
    const float4* p = reinterpret_cast<const float4*>(part + (size_t)n * 256 * D_A);
    float4 acc = make_float4(0.f, 0.f, 0.f, 0.f);
    #pragma unroll
    for (int s = c; s < 256; s += 4) acc = f4add(acc, p[(size_t)s * 64 + q]);
    red4[threadIdx.x] = acc;
    __syncthreads();
    if (threadIdx.x < 64) {
        float4 k = f4add(f4add(red4[q], red4[q + 64]),
                         f4add(red4[q + 128], red4[q + 192]));
        k = f4add(k, reinterpret_cast<const float4*>(b_k + n * D_A)[q]);
        const float4 wq = reinterpret_cast<const float4*>(
            W_q + ((size_t)t * 10 + t) * D_A)[q];
        const float4 bq = reinterpret_cast<const float4*>(b_q + t * D_A)[q];
        red[q] = k.x * (wq.x + bq.x) + k.y * (wq.y + bq.y)
               + k.z * (wq.z + bq.z) + k.w * (wq.w + bq.w);
    }
    __syncthreads();
    if (threadIdx.x < 32) {
        float v = red[threadIdx.x] + red[threadIdx.x + 32];
        #pragma unroll
        for (int off = 16; off; off >>= 1) v += __shfl_xor_sync(0xFFFFFFFFu, v, off);
        if (threadIdx.x == 0) expkq[n] = v;
    }
    cudaTriggerProgrammaticLaunchCompletion();
}

// out[j] = b_l[j] + reduce_{s<512} pG[s*512 + j];  8 blocks x 256 thr.
__global__ __launch_bounds__(256)
void fin_out(const float* __restrict__ part,
             const float* __restrict__ b_l,
             float* __restrict__ out)
{
    __shared__ float4 red4[256];
    const int ql = threadIdx.x % 16;            // quad within block
    const int c  = threadIdx.x / 16;            // 16 chunks
    const int jq = blockIdx.x * 16 + ql;        // quad in [0,128)
    cudaGridDependencySynchronize();
    const float4* p = reinterpret_cast<const float4*>(part);
    float4 acc = make_float4(0.f, 0.f, 0.f, 0.f);
    #pragma unroll 8
    for (int s = c; s < 512; s += 16) acc = f4add(acc, p[(size_t)s * 128 + jq]);
    red4[threadIdx.x] = acc;
    __syncthreads();
    #pragma unroll
    for (int off = 8; off >= 1; off >>= 1) {
        if (c < off) red4[threadIdx.x] = f4add(red4[threadIdx.x],
                                               red4[threadIdx.x + off * 16]);
        __syncthreads();
    }
    if (c == 0) {
        float4 v = f4add(red4[ql], reinterpret_cast<const float4*>(b_l)[jq]);
        reinterpret_cast<float4*>(out)[jq] = v;
    }
    cudaTriggerProgrammaticLaunchCompletion();
}

// ---------------------------------------------------------------------------
template<typename K, typename... A>
static inline void launch_pdl(K kern, dim3 g, dim3 b, A... args)
{
    cudaLaunchConfig_t cfg = {};
    cfg.gridDim = g;
    cfg.blockDim = b;
    cfg.stream = 0;
    cudaLaunchAttribute at[1];
    at[0].id = cudaLaunchAttributeProgrammaticStreamSerialization;
    at[0].val.programmaticStreamSerializationAllowed = 1;
    cfg.attrs = at;
    cfg.numAttrs = 1;
    cudaLaunchKernelEx(&cfg, kern, args...);
}

extern "C" void kernel_launch(void* const* d_in, const int* in_sizes, int n_in,
                              void* d_out, int out_size)
{
    const float* x     = (const float*)d_in[0];
    const float* W1    = (const float*)d_in[1];
    const float* b1    = (const float*)d_in[2];
    const float* W2    = (const float*)d_in[3];
    const float* b2    = (const float*)d_in[4];
    const float* W_exp = (const float*)d_in[5];
    const float* b_exp = (const float*)d_in[6];
    const float* W_v   = (const float*)d_in[7];
    const float* b_v   = (const float*)d_in[8];
    const float* W_k   = (const float*)d_in[9];
    const float* b_k   = (const float*)d_in[10];
    const float* W_q   = (const float*)d_in[11];
    const float* b_q   = (const float*)d_in[12];
    const float* W_t   = (const float*)d_in[13];
    const float* b_t   = (const float*)d_in[14];
    const float* W_l   = (const float*)d_in[15];
    const float* b_l   = (const float*)d_in[16];
    const int*   tid   = (const int*)d_in[17];
    float* out = (float*)d_out;

    float *pA, *pB, *h2, *pC, *pD, *pE, *res, *pF, *pG, *ekq;
    cudaGetSymbolAddress((void**)&pA, g_pA);
    cudaGetSymbolAddress((void**)&pB, g_pB);
    cudaGetSymbolAddress((void**)&h2, g_h2);
    cudaGetSymbolAddress((void**)&pC, g_pC);
    cudaGetSymbolAddress((void**)&pD, g_pD);
    cudaGetSymbolAddress((void**)&pE, g_pE);
    cudaGetSymbolAddress((void**)&res, g_res);
    cudaGetSymbolAddress((void**)&pF, g_pF);
    cudaGetSymbolAddress((void**)&pG, g_pG);
    cudaGetSymbolAddress((void**)&ekq, g_ekq);

    // A: pA = splitK(x @ W1)       16MB, 512 blocks (GRP=2), full prefetch
    launch_pdl(gemv_k<256, 16, 2048, 2, 0, 0, 1, false, false, 8>,
               dim3(4, 128, 1), dim3(256), W1, x, (const float*)nullptr, pA);
    // B: h1 fused; pB = splitK(h1 @ W2)   16MB, 512 blocks
    launch_pdl(gemv_k<256, 16, 2048, 2, 1, 256, 2048, true, false, 8>,
               dim3(4, 128, 1), dim3(256), W2, pA, b1, pB);
    // h2 = relu(reduce(pB) + b2)          1MB read, 8 blocks
    launch_pdl(fin_h2, dim3(8), dim3(256), pB, b2, h2);
    // C: pC[n] = splitK(h2 @ W_exp[n])    256MB, 1024 blocks, MODE 0 (8KB x)
    launch_pdl(gemv_k<256, 64, 2048, 1, 0, 0, 1, false, false, 0>,
               dim3(2, 32, 16), dim3(256), W_exp, h2, (const float*)nullptr, pC);
    // D+E merged, uniform 1024 blocks     288MB
    launch_pdl(gemv_DE, dim3(2, 32, 16), dim3(256), W_v, W_k, pC, b_exp, pE, pD);
    // expkq
    launch_pdl(fin_expkq, dim3(16), dim3(256), pD, b_k, W_q, b_q, tid, ekq);
    // res = ekq-weighted reduce(pE) + ekq.b_v     4MB read, 8 blocks
    launch_pdl(fin_res, dim3(8), dim3(256), pE, b_v, ekq, res);
    // F: pF = splitK(res @ W_t)           16MB, 512 blocks, MODE 0
    launch_pdl(gemv_k<256, 16, 2048, 2, 0, 0, 1, false, false, 8>,
               dim3(4, 128, 1), dim3(256), W_t, res, (const float*)nullptr, pF);
    // G: t fused; pG = splitK(t @ W_l)    4MB, 256 blocks (GRP=4)
    launch_pdl(gemv_k<256, 16, 512, 4, 1, 256, 2048, true, false, 4>,
               dim3(2, 128, 1), dim3(256), W_l, pF, b_t, pG);
    // out
    launch_pdl(fin_out, dim3(8), dim3(256), pG, b_l, out);
}

// round 12
// speedup vs baseline: 1.1586x; 1.1586x over previous
#include <cuda_runtime.h>
#include <cuda_bf16.h>
#include <cstddef>

// NetAE batch-1 forward: HBM-bound GEMV chain (~596MB fp32 weights/call).
// Round 12 (base = round 8, measured best 123.6us):
//  - attention score folded into DE: D-tile blocks dot their k-partial with q
//    in-kernel and emit ONE scalar per block (pDs) -> pD buffer (2MB traffic)
//    and the fin_expkq launch are ELIMINATED.
//  - F's prologue reconstructs ekq[16] from pDs + b_k.q (cheap, overlapped
//    with its 16MB register weight prefetch), then does the r8 MODE-2 staging.
//  - fin_out widened 2 -> 8 blocks.
// A, B, C, G identical to round 8. PDL with end-of-kernel trigger everywhere.

#define D_H    2048
#define D_A    256
#define N_EXP  16
#define D_OUT  512

__device__ float g_pA[128 * 2048];
__device__ float g_pB[128 * 2048];
__device__ float g_pC[16 * 32 * 2048];
__device__ float g_pDs[16 * 64];         // per-block k.q scalar partials
__device__ float g_pE[512 * 2048];       // UNSCALED V partials
__device__ float g_pF[128 * 2048];
__device__ float g_pG[256 * 512];

__device__ __forceinline__ float4 f4add(float4 a, float4 b) {
    return make_float4(a.x + b.x, a.y + b.y, a.z + b.z, a.w + b.w);
}

// ---------------------------------------------------------------------------
// Shared prologue (round-8 form): build sx[RPS] = x-slice [i0, i0+RPS).
//   MODE 0: sx[r] = xsrc[i0+r]
//   MODE 1: sx[r] = [relu](biasx[bb*NPREV+i0+r] + sum_{s<SPREV} xsrc[(bb*SPREV+s)*NPREV+i0+r])
// ---------------------------------------------------------------------------
template<int BLK, int RPS, int MODE, int SPREV, int NPREV, bool RELU_X, bool PREV_PER_B>
__device__ __forceinline__
void stage_x(float* sx, const float* __restrict__ xsrc,
             const float* __restrict__ biasx, int i0, int b)
{
    const int tid = threadIdx.x;
    if constexpr (MODE == 0) {
        for (int r = tid; r < RPS; r += BLK) sx[r] = xsrc[i0 + r];
        __syncthreads();
    } else {
        constexpr int NQ = RPS / 4;
        constexpr int CH = BLK / NQ;
        __shared__ float4 sxp4[BLK];
        const int q = tid % NQ;
        const int c = tid / NQ;
        const int bb = PREV_PER_B ? b : 0;
        const float4* p = reinterpret_cast<const float4*>(
            xsrc + ((size_t)bb * SPREV) * NPREV + i0);
        float4 v = make_float4(0.f, 0.f, 0.f, 0.f);
        #pragma unroll
        for (int s = c; s < SPREV; s += CH)
            v = f4add(v, p[(size_t)s * (NPREV / 4) + q]);
        sxp4[tid] = v;
        __syncthreads();
        if (tid < NQ) {
            float4 v2 = reinterpret_cast<const float4*>(
                            biasx + (size_t)bb * NPREV + i0)[tid];
            #pragma unroll
            for (int cc = 0; cc < CH; cc++) v2 = f4add(v2, sxp4[tid + cc * NQ]);
            if constexpr (RELU_X) {
                v2.x = fmaxf(v2.x, 0.f); v2.y = fmaxf(v2.y, 0.f);
                v2.z = fmaxf(v2.z, 0.f); v2.w = fmaxf(v2.w, 0.f);
            }
            reinterpret_cast<float4*>(sx)[tid] = v2;
        }
        __syncthreads();
    }
}

// Generic split-K GEMV stage. PF = rows prefetched into regs before the wait.
template<int BLK, int RPS, int N, int GRP, int MODE, int SPREV, int NPREV,
         bool RELU_X, bool PREV_PER_B, int PF>
__global__ __launch_bounds__(BLK)
void gemv_k(const float* __restrict__ W,
            const float* __restrict__ xsrc,
            const float* __restrict__ biasx,
            float* __restrict__ partOut)
{
    __shared__ float sx[RPS];
    const int tid   = threadIdx.x;
    const int slice = blockIdx.y;
    const int b     = blockIdx.z;
    const int S     = gridDim.y;
    const int i0    = slice * RPS;
    const int K     = S * RPS;

    constexpr int CT  = BLK / GRP;
    constexpr int RPG = RPS / GRP;
    const int g  = tid / CT;
    const int j  = (blockIdx.x * CT + (tid % CT)) * 4;
    const int r0 = g * RPG;
    const float* Wp = W + (size_t)b * K * N + (size_t)(i0 + r0) * N + j;

    float4 wreg[PF > 0 ? PF : 1];
    #pragma unroll
    for (int rr = 0; rr < PF; rr++)
        wreg[rr] = *reinterpret_cast<const float4*>(Wp + (size_t)rr * N);

    cudaGridDependencySynchronize();

    stage_x<BLK, RPS, MODE, SPREV, NPREV, RELU_X, PREV_PER_B>(sx, xsrc, biasx, i0, b);

    float4 acc = make_float4(0.f, 0.f, 0.f, 0.f);
    #pragma unroll
    for (int rr = 0; rr < PF; rr++) {
        const float xi = sx[r0 + rr];
        acc.x += xi * wreg[rr].x; acc.y += xi * wreg[rr].y;
        acc.z += xi * wreg[rr].z; acc.w += xi * wreg[rr].w;
    }
    #pragma unroll 16
    for (int rr = PF; rr < RPG; rr++) {
        const float4 w = *reinterpret_cast<const float4*>(Wp + (size_t)rr * N);
        const float xi = sx[r0 + rr];
        acc.x += xi * w.x; acc.y += xi * w.y;
        acc.z += xi * w.z; acc.w += xi * w.w;
    }
    *reinterpret_cast<float4*>(
        partOut + ((size_t)((b * S + slice) * GRP + g)) * N + j) = acc;
    cudaTriggerProgrammaticLaunchCompletion();
}

// ---------------------------------------------------------------------------
// Merged D+E stage, uniform 1024 blocks (round-8 tiling). grid = (2, 32, 16).
// D-tile now dots its k-partial with q in-kernel -> one scalar per block:
//   pDs[b*64 + slice*2 + xp] = sum_{64 rows x 128 a-cols} kpart[r,a]*q[a]
// ---------------------------------------------------------------------------
__global__ __launch_bounds__(256)
void gemv_DE(const float* __restrict__ Wv, const float* __restrict__ Wk,
             const float* __restrict__ pC, const float* __restrict__ b_exp,
             const float* __restrict__ W_q, const float* __restrict__ b_q,
             const int* __restrict__ task_id,
             float* __restrict__ pE, float* __restrict__ pDs)
{
    __shared__ float sx[64];
    __shared__ float redD[256];
    const int tid   = threadIdx.x;
    const int xp    = blockIdx.x;
    const int slice = blockIdx.y;
    const int b     = blockIdx.z;
    const int i0    = slice * 64;

    cudaGridDependencySynchronize();
    stage_x<256, 64, 1, 32, 2048, true, true>(sx, pC, b_exp, i0, b);

    // ---- E tile ----
    {
        const int j = (xp * 256 + tid) * 4;
        const float* Wp = Wv + (size_t)b * 2048 * 2048 + (size_t)i0 * 2048 + j;
        float4 acc = make_float4(0.f, 0.f, 0.f, 0.f);
        #pragma unroll 16
        for (int rr = 0; rr < 64; rr++) {
            const float4 w = *reinterpret_cast<const float4*>(Wp + (size_t)rr * 2048);
            const float xi = sx[rr];
            acc.x += xi * w.x; acc.y += xi * w.y;
            acc.z += xi * w.z; acc.w += xi * w.w;
        }
        *reinterpret_cast<float4*>(pE + ((size_t)(b * 32 + slice)) * 2048 + j) = acc;
    }
    // ---- D tile -> scalar k.q partial ----
    {
        const int g  = tid / 32;
        const int jd = xp * 128 + (tid % 32) * 4;
        const int r0 = g * 8;
        const float* Wp = Wk + (size_t)b * 2048 * 256 + (size_t)(i0 + r0) * 256 + jd;
        float4 acc = make_float4(0.f, 0.f, 0.f, 0.f);
        #pragma unroll
        for (int rr = 0; rr < 8; rr++) {
            const float4 w = *reinterpret_cast<const float4*>(Wp + (size_t)rr * 256);
            const float xi = sx[r0 + rr];
            acc.x += xi * w.x; acc.y += xi * w.y;
            acc.z += xi * w.z; acc.w += xi * w.w;
        }
        const int t = *task_id;
        const float4 wq = *reinterpret_cast<const float4*>(
            W_q + ((size_t)t * 10 + t) * D_A + jd);
        const float4 bq = *reinterpret_cast<const float4*>(b_q + t * D_A + jd);
        redD[tid] = acc.x * (wq.x + bq.x) + acc.y * (wq.y + bq.y)
                  + acc.z * (wq.z + bq.z) + acc.w * (wq.w + bq.w);
    }
    __syncthreads();
    #pragma unroll
    for (int off = 128; off >= 32; off >>= 1) {
        if (tid < off) redD[tid] += redD[tid + off];
        __syncthreads();
    }
    if (tid < 32) {
        float v = redD[tid];
        #pragma unroll
        for (int off = 16; off; off >>= 1) v += __shfl_xor_sync(0xFFFFFFFFu, v, off);
        if (tid == 0) pDs[b * 64 + slice * 2 + xp] = v;
    }
    cudaTriggerProgrammaticLaunchCompletion();
}

// ---------------------------------------------------------------------------
// F stage: custom prologue reconstructs ekq[16] from pDs + b_k.q, then does
// the r8 MODE-2 staging (ekq-weighted reduce of pE + ekq.b_v), then the GEMV
// vs W_t with full register prefetch. grid(2,128), 256 thr, RPS=16.
// ---------------------------------------------------------------------------
__global__ __launch_bounds__(256)
void gemv_F(const float* __restrict__ W_t, const float* __restrict__ pE,
            const float* __restrict__ pDs, const float* __restrict__ b_k,
            const float* __restrict__ W_q, const float* __restrict__ b_q,
            const float* __restrict__ b_v, const int* __restrict__ task_id,
            float* __restrict__ pF)
{
    __shared__ float sekq[16];
    __shared__ float tmp[256];
    __shared__ float4 sxp4[256];
    __shared__ float sx[16];
    const int tid = threadIdx.x;
    const int slice = blockIdx.y;
    const int i0 = slice * 16;
    const int j  = (blockIdx.x * 256 + tid) * 4;
    const float* Wp = W_t + (size_t)i0 * 2048 + j;

    float4 wreg[16];
    #pragma unroll
    for (int rr = 0; rr < 16; rr++)
        wreg[rr] = *reinterpret_cast<const float4*>(Wp + (size_t)rr * 2048);

    cudaGridDependencySynchronize();

    // ekq[n] = sum_{i<64} pDs[n*64+i] + dot(b_k[n], q)
    {
        const int t = *task_id;
        const int n = tid >> 4;
        const int l = tid & 15;
        float s = 0.f;
        #pragma unroll
        for (int k = 0; k < 16; k++) {
            const int a = l * 16 + k;
            const float qv = W_q[((size_t)t * 10 + t) * D_A + a] + b_q[t * D_A + a];
            s += b_k[n * D_A + a] * qv;
        }
        tmp[tid] = s;
        __syncthreads();
        if (tid < 16) {
            float v = 0.f;
            #pragma unroll
            for (int l2 = 0; l2 < 16; l2++) v += tmp[tid * 16 + l2];
            #pragma unroll
            for (int i = 0; i < 64; i++) v += pDs[tid * 64 + i];
            sekq[tid] = v;
        }
        __syncthreads();
    }

    // MODE-2 staging: sx[16] = ekq-weighted reduce of 512 pE rows + ekq.b_v
    {
        const int q4 = tid % 4;          // 4 quads (RPS=16)
        const int c  = tid / 4;          // 64 chunks
        const float4* p = reinterpret_cast<const float4*>(pE + i0);
        float4 v = make_float4(0.f, 0.f, 0.f, 0.f);
        #pragma unroll
        for (int s = c; s < 512; s += 64) {
            float4 w = p[(size_t)s * 512 + q4];
            const float sc = sekq[s >> 5];
            v.x += sc * w.x; v.y += sc * w.y;
            v.z += sc * w.z; v.w += sc * w.w;
        }
        sxp4[tid] = v;
        __syncthreads();
        if (tid < 4) {
            float4 v2 = make_float4(0.f, 0.f, 0.f, 0.f);
            #pragma unroll
            for (int cc = 0; cc < 64; cc++) v2 = f4add(v2, sxp4[tid + cc * 4]);
            #pragma unroll
            for (int n = 0; n < N_EXP; n++) {
                const float4 bq = reinterpret_cast<const float4*>(
                    b_v + (size_t)n * 2048 + i0)[tid];
                const float e = sekq[n];
                v2.x += e * bq.x; v2.y += e * bq.y;
                v2.z += e * bq.z; v2.w += e * bq.w;
            }
            reinterpret_cast<float4*>(sx)[tid] = v2;
        }
        __syncthreads();
    }

    float4 acc = make_float4(0.f, 0.f, 0.f, 0.f);
    #pragma unroll
    for (int rr = 0; rr < 16; rr++) {
        const float xi = sx[rr];
        acc.x += xi * wreg[rr].x; acc.y += xi * wreg[rr].y;
        acc.z += xi * wreg[rr].z; acc.w += xi * wreg[rr].w;
    }
    *reinterpret_cast<float4*>(pF + ((size_t)slice) * 2048 + j) = acc;
    cudaTriggerProgrammaticLaunchCompletion();
}

// out[j] = b_l[j] + reduce_{s<256} pG[s*512 + j];  8 blocks x 256 thr.
__global__ __launch_bounds__(256)
void fin_out(const float* __restrict__ part,
             const float* __restrict__ b_l,
             float* __restrict__ out)
{
    __shared__ float4 red4[256];
    const int ql = threadIdx.x % 16;
    const int c  = threadIdx.x / 16;            // 16 chunks
    const int jq = blockIdx.x * 16 + ql;        // quad in [0,128)
    cudaGridDependencySynchronize();
    const float4* p = reinterpret_cast<const float4*>(part);
    float4 acc = make_float4(0.f, 0.f, 0.f, 0.f);
    #pragma unroll 8
    for (int s = c; s < 256; s += 16) acc = f4add(acc, p[(size_t)s * 128 + jq]);
    red4[threadIdx.x] = acc;
    __syncthreads();
    #pragma unroll
    for (int off = 8; off >= 1; off >>= 1) {
        if (c < off) red4[threadIdx.x] = f4add(red4[threadIdx.x],
                                               red4[threadIdx.x + off * 16]);
        __syncthreads();
    }
    if (c == 0) {
        float4 v = f4add(red4[ql], reinterpret_cast<const float4*>(b_l)[jq]);
        reinterpret_cast<float4*>(out)[jq] = v;
    }
    cudaTriggerProgrammaticLaunchCompletion();
}

// ---------------------------------------------------------------------------
template<typename K, typename... A>
static inline void launch_pdl(K kern, dim3 g, dim3 b, A... args)
{
    cudaLaunchConfig_t cfg = {};
    cfg.gridDim = g;
    cfg.blockDim = b;
    cfg.stream = 0;
    cudaLaunchAttribute at[1];
    at[0].id = cudaLaunchAttributeProgrammaticStreamSerialization;
    at[0].val.programmaticStreamSerializationAllowed = 1;
    cfg.attrs = at;
    cfg.numAttrs = 1;
    cudaLaunchKernelEx(&cfg, kern, args...);
}

extern "C" void kernel_launch(void* const* d_in, const int* in_sizes, int n_in,
                              void* d_out, int out_size)
{
    const float* x     = (const float*)d_in[0];
    const float* W1    = (const float*)d_in[1];
    const float* b1    = (const float*)d_in[2];
    const float* W2    = (const float*)d_in[3];
    const float* b2    = (const float*)d_in[4];
    const float* W_exp = (const float*)d_in[5];
    const float* b_exp = (const float*)d_in[6];
    const float* W_v   = (const float*)d_in[7];
    const float* b_v   = (const float*)d_in[8];
    const float* W_k   = (const float*)d_in[9];
    const float* b_k   = (const float*)d_in[10];
    const float* W_q   = (const float*)d_in[11];
    const float* b_q   = (const float*)d_in[12];
    const float* W_t   = (const float*)d_in[13];
    const float* b_t   = (const float*)d_in[14];
    const float* W_l   = (const float*)d_in[15];
    const float* b_l   = (const float*)d_in[16];
    const int*   tid   = (const int*)d_in[17];
    float* out = (float*)d_out;

    float *pA, *pB, *pC, *pDs, *pE, *pF, *pG;
    cudaGetSymbolAddress((void**)&pA, g_pA);
    cudaGetSymbolAddress((void**)&pB, g_pB);
    cudaGetSymbolAddress((void**)&pC, g_pC);
    cudaGetSymbolAddress((void**)&pDs, g_pDs);
    cudaGetSymbolAddress((void**)&pE, g_pE);
    cudaGetSymbolAddress((void**)&pF, g_pF);
    cudaGetSymbolAddress((void**)&pG, g_pG);

    // A: pA = splitK(x @ W1)             16MB, full register prefetch
    launch_pdl(gemv_k<256, 16, 2048, 1, 0, 0, 1, false, false, 16>,
               dim3(2, 128, 1), dim3(256), W1, x, (const float*)nullptr, pA);
    // B: h1 fused; pB = splitK(h1 @ W2)   16MB
    launch_pdl(gemv_k<256, 16, 2048, 1, 1, 128, 2048, true, false, 16>,
               dim3(2, 128, 1), dim3(256), W2, pA, b1, pB);
    // C: h2 fused; pC[n] = splitK(h2 @ W_exp[n])   256MB, 1024 blocks
    launch_pdl(gemv_k<256, 64, 2048, 1, 1, 128, 2048, true, false, 0>,
               dim3(2, 32, 16), dim3(256), W_exp, pB, b2, pC);
    // D+E merged + in-kernel k.q dot      288MB, uniform 1024 blocks
    launch_pdl(gemv_DE, dim3(2, 32, 16), dim3(256),
               W_v, W_k, pC, b_exp, W_q, b_q, tid, pE, pDs);
    // F: ekq reconstructed in-prologue; res fused; pF = splitK(res @ W_t)  16MB
    launch_pdl(gemv_F, dim3(2, 128, 1), dim3(256),
               W_t, pE, pDs, b_k, W_q, b_q, b_v, tid, pF);
    // G: t fused; pG = splitK(t @ W_l)    4MB
    launch_pdl(gemv_k<256, 16, 512, 2, 1, 128, 2048, true, false, 8>,
               dim3(1, 128, 1), dim3(256), W_l, pF, b_t, pG);
    // out
    launch_pdl(fin_out, dim3(8), dim3(256), pG, b_l, out);
}